// round 14
// baseline (speedup 1.0000x reference)
#include <cuda_runtime.h>
#include <cstdint>

#define Bv 4
#define Nv 512
#define Dv 256
#define Lv 64

typedef unsigned long long ull;

// w-folded projection [b][l][n] (512 KB) and symmetric dist buffer (4 MB)
__device__ float g_xh[Bv * Lv * Nv];
__device__ float g_dist[Bv * Nv * Nv];
// device barrier (replay-safe: count resets, release monotone)
__device__ unsigned g_count = 0, g_release = 0;

__device__ __forceinline__ ull pk2(float a) {
    ull r;
    asm("mov.b64 %0, {%1, %2};" : "=l"(r) : "f"(a), "f"(a));
    return r;
}
__device__ __forceinline__ ull add2(ull a, ull b) {
    ull r;
    asm("add.rn.f32x2 %0, %1, %2;" : "=l"(r) : "l"(a), "l"(b));
    return r;
}
__device__ __forceinline__ float lo2(ull a) {
    float x, y;
    asm("mov.b64 {%0, %1}, %2;" : "=f"(x), "=f"(y) : "l"(a));
    return x;
}
__device__ __forceinline__ float hi2(ull a) {
    float x, y;
    asm("mov.b64 {%0, %1}, %2;" : "=f"(x), "=f"(y) : "l"(a));
    return y;
}

__device__ __forceinline__ void grid_barrier(int tid) {
    __syncthreads();
    if (tid == 0) {
        __threadfence();
        unsigned snap = *(volatile unsigned*)&g_release;
        unsigned old  = atomicAdd(&g_count, 1);
        if (old == 127u) {
            g_count = 0;
            __threadfence();
            atomicAdd(&g_release, 1);
        } else {
            while (*(volatile unsigned*)&g_release == snap) __nanosleep(32);
        }
        __threadfence();
    }
    __syncthreads();
}

// ---------------------------------------------------------------------------
// Grid 128 = (b, tile t of 16 rows), 1024 threads, ~141 KB smem, 1 CTA/SM.
// Symmetric band: tile t computes j-blocks t+1..t+16 (256 cols), writes
// block + transpose to g_dist; diagonal from si2. Parallel phase A
// (1 output/thread). adj prefetched to smem at entry.
// Smem floats:
//   sjb [0,     17408)  64x272 band   (phase-A overlay: Wl 64x256 at 0)
//   si2 [17408, 19456)  64x16 ull {-wv,-wv}
//   psum[19456, 23552)  16x256
//   adjs[23552, 31744)  16x512
//   red [31744, 31808)
//   xs  [31808, 35968)  16x260 (phase A only)
// ---------------------------------------------------------------------------
__global__ __launch_bounds__(1024, 1) void fused_kernel(
    const float* __restrict__ x, const float* __restrict__ adj,
    const float* __restrict__ W, const float* __restrict__ lw,
    float* __restrict__ out) {
    extern __shared__ float sm[];
    float* sjb  = sm;
    ull*   si2  = (ull*)(sm + 17408);
    float* psum = sm + 19456;
    float* adjs = sm + 23552;
    float* red  = sm + 31744;
    float* xs   = sm + 31808;
    float* Wl   = sm;                 // phase A overlay

    int bid = blockIdx.x;
    int b = bid >> 5, i0 = (bid & 31) << 4;
    int tid = threadIdx.x;

    // ---- adj tile prefetch (independent) -----------------------------------
    {
        const float4* asrc = (const float4*)(adj + (size_t)(b * Nv + i0) * Nv);
        float4* adst = (float4*)adjs;
        adst[tid]        = asrc[tid];
        adst[tid + 1024] = asrc[tid + 1024];
    }

    // ---- Phase A staging ----------------------------------------------------
    {
        int r = tid >> 6, d4 = tid & 63;           // 1024 = 16*64
        *(float4*)&xs[r * 260 + d4 * 4] =
            *(const float4*)&x[(size_t)(b * Nv + i0 + r) * Dv + d4 * 4];
    }
#pragma unroll
    for (int k = 0; k < 4; ++k)
        ((float4*)Wl)[tid + k * 1024] = ((const float4*)W)[tid + k * 1024];
    __syncthreads();

    // ---- Phase A compute: one (r,l) output per thread -----------------------
    {
        int r = tid & 15, l = tid >> 4;
        const float* xp = xs + r * 260;
        const float* wp = Wl + l * 256;
        float acc0 = 0.f, acc1 = 0.f;
#pragma unroll 8
        for (int d4 = 0; d4 < 64; ++d4) {
            float4 xv = *(const float4*)&xp[d4 * 4];
            float4 wv = *(const float4*)&wp[d4 * 4];
            acc0 = fmaf(xv.x, wv.x, acc0);
            acc1 = fmaf(xv.y, wv.y, acc1);
            acc0 = fmaf(xv.z, wv.z, acc0);
            acc1 = fmaf(xv.w, wv.w, acc1);
        }
        float a = (acc0 + acc1) * lw[l];
        g_xh[b * (Lv * Nv) + l * Nv + i0 + r] = a;
        si2[l * 16 + r] = pk2(-a);
    }
    __syncthreads();

    // ---- diagonal 16x16 block from si2 (lo halves hold -w*xhat) -------------
    if (tid < 256) {
        int r = tid >> 4, c = tid & 15;
        const float* s = (const float*)si2;
        float acc = 0.f;
#pragma unroll 8
        for (int l = 0; l < 64; ++l)
            acc += fabsf(s[(l * 16 + r) * 2] - s[(l * 16 + c) * 2]);
        g_dist[(size_t)(b * Nv + i0 + r) * Nv + i0 + c] = acc;
    }

    grid_barrier(tid);

    // ---- stage j-band: window [i0, i0+272) mod 512 (overwrites Wl) ----------
    for (int idx = tid; idx < 4352; idx += 1024) {
        int l = idx / 68, c4 = idx - l * 68;
        int jg4 = ((i0 >> 2) + c4) & 127;
        *(float4*)(sjb + l * 272 + c4 * 4) =
            *(const float4*)(g_xh + b * (Lv * Nv) + l * Nv + jg4 * 4);
    }
    __syncthreads();

    // ---- mainloop: 16 rows x 256 band cols x 64 l ---------------------------
    int w    = tid >> 5;
    int lane = tid & 31;
    int rg = w & 7;            // 2 rows: 2rg, 2rg+1
    int jq = (w >> 3) & 1;     // 128-col half of band
    int lh = w >> 4;           // l half

    const float* sjp = sjb + lh * 32 * 272 + 16 + jq * 128 + lane * 4;
    const ull*   sip = si2 + lh * 32 * 16 + rg * 2;
    const ull ABS2 = 0x7FFFFFFF7FFFFFFFull;
    ull a00 = 0, a01 = 0, a10 = 0, a11 = 0;

#pragma unroll
    for (int l = 0; l < 32; ++l) {
        ulonglong2 j01 = *(const ulonglong2*)(sjp + l * 272);
        ulonglong2 nab = *(const ulonglong2*)(sip + l * 16);
        a00 = add2(a00, add2(j01.x, nab.x) & ABS2);
        a01 = add2(a01, add2(j01.y, nab.x) & ABS2);
        a10 = add2(a10, add2(j01.x, nab.y) & ABS2);
        a11 = add2(a11, add2(j01.y, nab.y) & ABS2);
    }

    // ---- merge l-halves in psum ---------------------------------------------
    int prow = rg * 2, pcol = jq * 128 + lane * 4;
    if (lh == 0) {
        *(float4*)&psum[prow * 256 + pcol] =
            make_float4(lo2(a00), hi2(a00), lo2(a01), hi2(a01));
        *(float4*)&psum[(prow + 1) * 256 + pcol] =
            make_float4(lo2(a10), hi2(a10), lo2(a11), hi2(a11));
    }
    __syncthreads();
    if (lh == 1) {
        float4 p0 = *(const float4*)&psum[prow * 256 + pcol];
        p0.x += lo2(a00); p0.y += hi2(a00);
        p0.z += lo2(a01); p0.w += hi2(a01);
        *(float4*)&psum[prow * 256 + pcol] = p0;
        float4 p1 = *(const float4*)&psum[(prow + 1) * 256 + pcol];
        p1.x += lo2(a10); p1.y += hi2(a10);
        p1.z += lo2(a11); p1.w += hi2(a11);
        *(float4*)&psum[(prow + 1) * 256 + pcol] = p1;
    }
    __syncthreads();

    // ---- direct write: rows i0.., band cols -> g_dist -----------------------
    {
        int row = tid >> 6, c4 = tid & 63;
        float4 v = *(const float4*)&psum[row * 256 + c4 * 4];
        int jg = (i0 + 16 + c4 * 4) & 511;
        *(float4*)&g_dist[(size_t)(b * Nv + i0 + row) * Nv + jg] = v;
    }
    // ---- transpose write: rows = band cols, cols = own rows -----------------
    {
        int jloc = tid >> 2, cg = tid & 3;
        float4 v;
        v.x = psum[(cg * 4 + 0) * 256 + jloc];
        v.y = psum[(cg * 4 + 1) * 256 + jloc];
        v.z = psum[(cg * 4 + 2) * 256 + jloc];
        v.w = psum[(cg * 4 + 3) * 256 + jloc];
        int jg = (i0 + 16 + jloc) & 511;
        *(float4*)&g_dist[(size_t)(b * Nv + jg) * Nv + i0 + cg * 4] = v;
    }

    grid_barrier(tid);

    // ---- epilogue over own 16 full rows (adj from smem) ---------------------
    {
        int row  = w >> 1;
        int half = w & 1;
        int c0 = half * 256 + lane * 4;
        int c1 = c0 + 128;
        const float* drow = g_dist + (size_t)(b * Nv + i0 + row) * Nv;

        float4 v0 = __ldcg((const float4*)(drow + c0));
        float4 v1 = __ldcg((const float4*)(drow + c1));
        v0.x = v0.x > 0.f ? v0.x : 0.01f * v0.x;
        v0.y = v0.y > 0.f ? v0.y : 0.01f * v0.y;
        v0.z = v0.z > 0.f ? v0.z : 0.01f * v0.z;
        v0.w = v0.w > 0.f ? v0.w : 0.01f * v0.w;
        v1.x = v1.x > 0.f ? v1.x : 0.01f * v1.x;
        v1.y = v1.y > 0.f ? v1.y : 0.01f * v1.y;
        v1.z = v1.z > 0.f ? v1.z : 0.01f * v1.z;
        v1.w = v1.w > 0.f ? v1.w : 0.01f * v1.w;

        const float* arow = adjs + row * Nv;
        float4 A0 = *(const float4*)&arow[c0];
        float4 A1 = *(const float4*)&arow[c1];
        // no row-max: dist bounded (~36 +/- 5), exp finite in fp32
        float4 e0, e1;
        e0.x = A0.x * __expf(v0.x);
        e0.y = A0.y * __expf(v0.y);
        e0.z = A0.z * __expf(v0.z);
        e0.w = A0.w * __expf(v0.w);
        e1.x = A1.x * __expf(v1.x);
        e1.y = A1.y * __expf(v1.y);
        e1.z = A1.z * __expf(v1.z);
        e1.w = A1.w * __expf(v1.w);

        float sr = e0.x + e0.y + e0.z + e0.w + e1.x + e1.y + e1.z + e1.w;
#pragma unroll
        for (int o = 16; o; o >>= 1)
            sr += __shfl_xor_sync(0xffffffffu, sr, o);
        if (lane == 0) red[row * 2 + half] = sr;
        __syncthreads();
        float rs = 1.0f / (red[row * 2] + red[row * 2 + 1]);

        float* orow = out + (size_t)(b * Nv + i0 + row) * Nv;
        float4 o4;
        o4.x = e0.x * rs + 1e-10f; o4.y = e0.y * rs + 1e-10f;
        o4.z = e0.z * rs + 1e-10f; o4.w = e0.w * rs + 1e-10f;
        *(float4*)&orow[c0] = o4;
        o4.x = e1.x * rs + 1e-10f; o4.y = e1.y * rs + 1e-10f;
        o4.z = e1.z * rs + 1e-10f; o4.w = e1.w * rs + 1e-10f;
        *(float4*)&orow[c1] = o4;
    }
}

extern "C" void kernel_launch(void* const* d_in, const int* in_sizes, int n_in,
                              void* d_out, int out_size) {
    (void)in_sizes; (void)n_in; (void)out_size;
    const float* x   = (const float*)d_in[0];
    const float* adj = (const float*)d_in[1];
    const float* W   = (const float*)d_in[2];
    const float* lw  = (const float*)d_in[3];
    float* out = (float*)d_out;

    const int smem = 35968 * 4;   // 143872 B
    cudaFuncSetAttribute(fused_kernel,
                         cudaFuncAttributeMaxDynamicSharedMemorySize, smem);
    cudaFuncSetAttribute(fused_kernel,
                         cudaFuncAttributePreferredSharedMemoryCarveout,
                         cudaSharedmemCarveoutMaxShared);

    fused_kernel<<<Bv * 32, 1024, smem>>>(x, adj, W, lw, out);
}